// round 7
// baseline (speedup 1.0000x reference)
#include <cuda_runtime.h>
#include <cuda_bf16.h>

#define N_NODES   100000
#define N_EDGES   3200000
#define E_TOT     (N_EDGES + N_NODES)   // self loops appended
#define IN_DIM    512
#define HEADS     4
#define C1        8
#define C2        4
#define HC1       (HEADS*C1)   // 32
#define HC2       (HEADS*C2)   // 16
#define N_GRAPHS  64
#define OUT_DIM   10

#define SCAN_BS   1024
#define N_SCAN_BLOCKS ((N_NODES + SCAN_BS - 1) / SCAN_BS)   // 98

typedef unsigned long long ull;

// ---------------- device scratch ----------------
__device__ __align__(16) float g_h1 [(size_t)N_NODES * HC1];
__device__ __align__(16) float g_es1[(size_t)N_NODES * HEADS];
__device__ __align__(16) float g_ed1[(size_t)N_NODES * HEADS];

__device__ __align__(16) float g_h2 [(size_t)N_NODES * HC2];
__device__ __align__(16) float g_es2[(size_t)N_NODES * HEADS];
__device__ __align__(16) float g_ed2[(size_t)N_NODES * HEADS];

__device__ __align__(16) float g_pool[N_GRAPHS * HC2];
__device__ float g_cnt [N_GRAPHS];

__device__ int g_deg[N_NODES];
__device__ int g_off[N_NODES + 1];
__device__ int g_pos[N_NODES];
__device__ int g_csr[E_TOT];
__device__ int g_blocksum[N_SCAN_BLOCKS];
__device__ int g_blockoff[N_SCAN_BLOCKS];

__device__ int g_is64;

// ---------------- helpers ----------------
__device__ __forceinline__ float lrelu(float v) { return v >= 0.f ? v : 0.2f * v; }

__device__ __forceinline__ void red4(float* p, float a, float b, float c, float d) {
    asm volatile("red.global.add.v4.f32 [%0], {%1,%2,%3,%4};"
                 :: "l"(p), "f"(a), "f"(b), "f"(c), "f"(d) : "memory");
}

__device__ __forceinline__ ull pack2(float a, float b) {
    ull r; asm("mov.b64 %0, {%1, %2};" : "=l"(r) : "f"(a), "f"(b)); return r;
}
__device__ __forceinline__ ull fma2(ull a, ull b, ull c) {
    ull d; asm("fma.rn.f32x2 %0, %1, %2, %3;" : "=l"(d) : "l"(a), "l"(b), "l"(c)); return d;
}
__device__ __forceinline__ void unpack2(ull v, float& a, float& b) {
    asm("mov.b64 {%0, %1}, %2;" : "=f"(a), "=f"(b) : "l"(v));
}

__device__ __forceinline__ void load_edge(const void* ei, int i, int is64, int& s, int& d) {
    if (i < N_EDGES) {
        if (is64) {
            const long long* p = (const long long*)ei;
            s = (int)p[i];
            d = (int)p[(size_t)N_EDGES + i];
        } else {
            const int* p = (const int*)ei;
            s = p[i];
            d = p[(size_t)N_EDGES + i];
        }
    } else {
        s = d = i - N_EDGES;
    }
}

// ---------------- detect (parallel) + init ----------------
__global__ void detect_kernel(const void* ei) {
    const unsigned long long* p = (const unsigned long long*)ei;
    int big = (p[threadIdx.x] >= (unsigned long long)N_NODES) ? 1 : 0;
    unsigned any_big = __ballot_sync(0xffffffffu, big);
    __shared__ unsigned sb[8];
    if ((threadIdx.x & 31) == 0) sb[threadIdx.x >> 5] = any_big;
    __syncthreads();
    if (threadIdx.x == 0) {
        unsigned m = 0;
        #pragma unroll
        for (int i = 0; i < 8; i++) m |= sb[i];
        g_is64 = (m == 0) ? 1 : 0;
    }
}

__global__ void init_kernel() {
    int t = blockIdx.x * blockDim.x + threadIdx.x;
    if (t < N_NODES) g_deg[t] = 0;
    if (t < N_GRAPHS * HC2) g_pool[t] = 0.f;
    if (t < N_GRAPHS)       g_cnt[t]  = 0.f;
}

// ---------------- CSR build ----------------
__global__ void count_kernel(const void* __restrict__ ei) {
    int i = blockIdx.x * blockDim.x + threadIdx.x;
    if (i >= E_TOT) return;
    int d;
    if (i < N_EDGES) {
        if (g_is64) d = (int)((const long long*)ei)[(size_t)N_EDGES + i];
        else        d = ((const int*)ei)[(size_t)N_EDGES + i];
    } else {
        d = i - N_EDGES;
    }
    atomicAdd(&g_deg[d], 1);
}

__global__ void scan1_kernel() {
    __shared__ int sm[SCAN_BS];
    const int t = threadIdx.x;
    const int idx = blockIdx.x * SCAN_BS + t;
    int v = (idx < N_NODES) ? g_deg[idx] : 0;
    sm[t] = v;
    __syncthreads();
    #pragma unroll
    for (int off = 1; off < SCAN_BS; off <<= 1) {
        int u = (t >= off) ? sm[t - off] : 0;
        __syncthreads();
        sm[t] += u;
        __syncthreads();
    }
    if (idx < N_NODES) g_off[idx] = sm[t] - v;
    if (t == SCAN_BS - 1) g_blocksum[blockIdx.x] = sm[t];
}

__global__ void scan2_kernel() {
    __shared__ int sm[128];
    const int t = threadIdx.x;
    int v = (t < N_SCAN_BLOCKS) ? g_blocksum[t] : 0;
    sm[t] = v;
    __syncthreads();
    #pragma unroll
    for (int off = 1; off < 128; off <<= 1) {
        int u = (t >= off) ? sm[t - off] : 0;
        __syncthreads();
        sm[t] += u;
        __syncthreads();
    }
    if (t < N_SCAN_BLOCKS) g_blockoff[t] = sm[t] - v;
}

__global__ void scan3_kernel() {
    const int idx = blockIdx.x * blockDim.x + threadIdx.x;
    if (idx < N_NODES) {
        int o = g_off[idx] + g_blockoff[blockIdx.x];
        g_off[idx] = o;
        g_pos[idx] = o;
    }
    if (idx == 0) g_off[N_NODES] = E_TOT;
}

__global__ void scatter_kernel(const void* __restrict__ ei) {
    int i = blockIdx.x * blockDim.x + threadIdx.x;
    if (i >= E_TOT) return;
    int s, d;
    load_edge(ei, i, g_is64, s, d);
    int p = atomicAdd(&g_pos[d], 1);
    g_csr[p] = s;
}

// ---------------- gemm1: h1 = x @ W1 (512->32), 8x8 tile, packed f32x2 FMA ----
#define G1_BN 256
#define G1_BK 32
__global__ __launch_bounds__(128) void gemm1_kernel(const float* __restrict__ x,
                                                    const float* __restrict__ W1,
                                                    const float* __restrict__ a_src,
                                                    const float* __restrict__ a_dst) {
    __shared__ float sX[G1_BN][36];
    __shared__ float sW[G1_BK][36];
    const int tid = threadIdx.x;
    const int nbase = blockIdx.x * G1_BN;
    const int ng = tid >> 2;
    const int cg = tid & 3;
    const int c0 = cg * 8;

    // acc[j][q] = packed cols (c0+2q, c0+2q+1) for node ng + j*32
    ull acc[8][4];
    #pragma unroll
    for (int j = 0; j < 8; j++)
        #pragma unroll
        for (int q = 0; q < 4; q++) acc[j][q] = 0ull;   // bits of (0.f, 0.f)

    for (int k0 = 0; k0 < IN_DIM; k0 += G1_BK) {
        __syncthreads();
        for (int i = tid; i < G1_BN * (G1_BK / 4); i += 128) {
            int n = i >> 3, kv = i & 7;
            float4 v = make_float4(0,0,0,0);
            if (nbase + n < N_NODES)
                v = *(const float4*)(x + (size_t)(nbase + n) * IN_DIM + k0 + kv * 4);
            *(float4*)&sX[n][kv * 4] = v;
        }
        for (int i = tid; i < G1_BK * 32; i += 128) {
            int k = i >> 5, c = i & 31;
            sW[k][c] = W1[(size_t)(k0 + k) * 32 + c];
        }
        __syncthreads();
        #pragma unroll
        for (int k4 = 0; k4 < G1_BK; k4 += 4) {
            float4 xt[8];
            #pragma unroll
            for (int j = 0; j < 8; j++) xt[j] = *(const float4*)&sX[ng + j * 32][k4];
            #pragma unroll
            for (int kk = 0; kk < 4; kk++) {
                const ull* wp = (const ull*)&sW[k4 + kk][c0];   // 8B-aligned (c0 mult of 8 floats, row 144B)
                ull w0 = wp[0], w1 = wp[1], w2 = wp[2], w3 = wp[3];
                #pragma unroll
                for (int j = 0; j < 8; j++) {
                    float xv = (kk == 0) ? xt[j].x : (kk == 1) ? xt[j].y
                             : (kk == 2) ? xt[j].z : xt[j].w;
                    ull xx = pack2(xv, xv);
                    acc[j][0] = fma2(xx, w0, acc[j][0]);
                    acc[j][1] = fma2(xx, w1, acc[j][1]);
                    acc[j][2] = fma2(xx, w2, acc[j][2]);
                    acc[j][3] = fma2(xx, w3, acc[j][3]);
                }
            }
        }
    }

    float as0 = a_src[c0+0], as1 = a_src[c0+1], as2 = a_src[c0+2], as3 = a_src[c0+3];
    float as4 = a_src[c0+4], as5 = a_src[c0+5], as6 = a_src[c0+6], as7 = a_src[c0+7];
    float ad0 = a_dst[c0+0], ad1 = a_dst[c0+1], ad2 = a_dst[c0+2], ad3 = a_dst[c0+3];
    float ad4 = a_dst[c0+4], ad5 = a_dst[c0+5], ad6 = a_dst[c0+6], ad7 = a_dst[c0+7];
    #pragma unroll
    for (int j = 0; j < 8; j++) {
        int n = nbase + ng + j * 32;
        if (n >= N_NODES) continue;
        float a0,a1,a2,a3,a4,a5,a6,a7;
        unpack2(acc[j][0], a0, a1);
        unpack2(acc[j][1], a2, a3);
        unpack2(acc[j][2], a4, a5);
        unpack2(acc[j][3], a6, a7);
        *(float4*)&g_h1[(size_t)n * HC1 + c0]     = make_float4(a0,a1,a2,a3);
        *(float4*)&g_h1[(size_t)n * HC1 + c0 + 4] = make_float4(a4,a5,a6,a7);
        float es = a0*as0 + a1*as1 + a2*as2 + a3*as3 + a4*as4 + a5*as5 + a6*as6 + a7*as7;
        float ed = a0*ad0 + a1*ad1 + a2*ad2 + a3*ad3 + a4*ad4 + a5*ad5 + a6*ad6 + a7*ad7;
        g_es1[(size_t)n * HEADS + cg] = es;
        g_ed1[(size_t)n * HEADS + cg] = ed;
    }
}

// ---------------- agg1: coalesced GAT layer-1 aggregation + fused gemm2 ------
__global__ __launch_bounds__(256) void agg1_kernel(const float* __restrict__ b1,
                                                   const float* __restrict__ W2,
                                                   const float* __restrict__ a_src2,
                                                   const float* __restrict__ a_dst2) {
    __shared__ float sW2[HC1 * HC2];
    __shared__ __align__(16) float sB1[HC1];
    __shared__ float sA2s[HC2], sA2d[HC2];
    {
        const int t = threadIdx.x;
        for (int i = t; i < HC1 * HC2; i += 256) sW2[i] = W2[i];
        if (t < HC1) sB1[t] = b1[t];
        if (t < HC2) { sA2s[t] = a_src2[t]; sA2d[t] = a_dst2[t]; }
        __syncthreads();
    }

    const int warp = (blockIdx.x * blockDim.x + threadIdx.x) >> 5;
    if (warp >= N_NODES) return;
    const int lane = threadIdx.x & 31;
    const int d    = warp;
    const int beg  = g_off[d];
    const int end  = g_off[d + 1];
    const int e    = lane >> 3;
    const int p    = lane & 7;
    const int head = p >> 1;
    const float4 edv = *(const float4*)(g_ed1 + (size_t)d * 4);

    float4 den = make_float4(0,0,0,0);
    float4 acc = make_float4(0,0,0,0);

    const int iters = (end - beg + 3) >> 2;
    for (int it = 0; it < iters; ++it) {
        const int base = beg + it * 4;
        int s_l = -1;
        if (lane < 4 && base + lane < end) s_l = g_csr[base + lane];
        const int s = __shfl_sync(0xffffffffu, s_l, e);

        float4 w4 = make_float4(0,0,0,0);
        if (lane < 4 && s_l >= 0) {
            float4 a = *(const float4*)(g_es1 + (size_t)s_l * 4);
            w4.x = __expf(lrelu(a.x + edv.x));
            w4.y = __expf(lrelu(a.y + edv.y));
            w4.z = __expf(lrelu(a.z + edv.z));
            w4.w = __expf(lrelu(a.w + edv.w));
            den.x += w4.x; den.y += w4.y; den.z += w4.z; den.w += w4.w;
        }
        float wx = __shfl_sync(0xffffffffu, w4.x, e);
        float wy = __shfl_sync(0xffffffffu, w4.y, e);
        float wz = __shfl_sync(0xffffffffu, w4.z, e);
        float ww = __shfl_sync(0xffffffffu, w4.w, e);
        float w = head == 0 ? wx : head == 1 ? wy : head == 2 ? wz : ww;

        if (s >= 0) {
            float4 hv = *(const float4*)(g_h1 + (size_t)s * HC1 + p * 4);
            acc.x += w * hv.x; acc.y += w * hv.y;
            acc.z += w * hv.z; acc.w += w * hv.w;
        }
    }

    #pragma unroll
    for (int o = 8; o <= 16; o <<= 1) {
        acc.x += __shfl_xor_sync(0xffffffffu, acc.x, o);
        acc.y += __shfl_xor_sync(0xffffffffu, acc.y, o);
        acc.z += __shfl_xor_sync(0xffffffffu, acc.z, o);
        acc.w += __shfl_xor_sync(0xffffffffu, acc.w, o);
    }
    #pragma unroll
    for (int o = 1; o <= 2; o <<= 1) {
        den.x += __shfl_xor_sync(0xffffffffu, den.x, o);
        den.y += __shfl_xor_sync(0xffffffffu, den.y, o);
        den.z += __shfl_xor_sync(0xffffffffu, den.z, o);
        den.w += __shfl_xor_sync(0xffffffffu, den.w, o);
    }
    float dnx = __shfl_sync(0xffffffffu, den.x, 0);
    float dny = __shfl_sync(0xffffffffu, den.y, 0);
    float dnz = __shfl_sync(0xffffffffu, den.z, 0);
    float dnw = __shfl_sync(0xffffffffu, den.w, 0);
    float dh  = head == 0 ? dnx : head == 1 ? dny : head == 2 ? dnz : dnw;
    float ih  = 1.f / (dh + 1e-16f);

    float4 bb = *(const float4*)&sB1[p * 4];
    float r0 = fmaxf(acc.x * ih + bb.x, 0.f);
    float r1 = fmaxf(acc.y * ih + bb.y, 0.f);
    float r2 = fmaxf(acc.z * ih + bb.z, 0.f);
    float r3 = fmaxf(acc.w * ih + bb.w, 0.f);

    const int k0 = p * 4, c0 = e * 4;
    float4 pc = make_float4(0,0,0,0);
    #pragma unroll
    for (int kk = 0; kk < 4; kk++) {
        float rv = kk == 0 ? r0 : kk == 1 ? r1 : kk == 2 ? r2 : r3;
        const float* wrow = &sW2[(k0 + kk) * HC2 + c0];
        pc.x += rv * wrow[0]; pc.y += rv * wrow[1];
        pc.z += rv * wrow[2]; pc.w += rv * wrow[3];
    }
    #pragma unroll
    for (int o = 1; o <= 4; o <<= 1) {
        pc.x += __shfl_xor_sync(0xffffffffu, pc.x, o);
        pc.y += __shfl_xor_sync(0xffffffffu, pc.y, o);
        pc.z += __shfl_xor_sync(0xffffffffu, pc.z, o);
        pc.w += __shfl_xor_sync(0xffffffffu, pc.w, o);
    }
    if (p == 0) {
        *(float4*)&g_h2[(size_t)d * HC2 + c0] = pc;
        float es = pc.x * sA2s[c0] + pc.y * sA2s[c0+1] + pc.z * sA2s[c0+2] + pc.w * sA2s[c0+3];
        float ed = pc.x * sA2d[c0] + pc.y * sA2d[c0+1] + pc.z * sA2d[c0+2] + pc.w * sA2d[c0+3];
        g_es2[(size_t)d * HEADS + e] = es;
        g_ed2[(size_t)d * HEADS + e] = ed;
    }
}

// ---------------- agg2: coalesced layer-2 aggregation + fused relu+pool ------
__global__ __launch_bounds__(256) void agg2_kernel(const float* __restrict__ b2,
                                                   const void* __restrict__ batch) {
    __shared__ __align__(16) float sB2[HC2];
    if (threadIdx.x < HC2) sB2[threadIdx.x] = b2[threadIdx.x];
    __syncthreads();

    const int warp = (blockIdx.x * blockDim.x + threadIdx.x) >> 5;
    if (warp >= N_NODES) return;
    const int lane = threadIdx.x & 31;
    const int d    = warp;
    const int beg  = g_off[d];
    const int end  = g_off[d + 1];
    const int sub  = lane >> 2;
    const int p    = lane & 3;
    const float4 edv = *(const float4*)(g_ed2 + (size_t)d * 4);

    float4 den = make_float4(0,0,0,0);
    float4 acc = make_float4(0,0,0,0);

    const int iters = (end - beg + 7) >> 3;
    for (int it = 0; it < iters; ++it) {
        const int base = beg + it * 8;
        int s_l = -1;
        if (lane < 8 && base + lane < end) s_l = g_csr[base + lane];
        const int s = __shfl_sync(0xffffffffu, s_l, sub);

        float4 w4 = make_float4(0,0,0,0);
        if (lane < 8 && s_l >= 0) {
            float4 a = *(const float4*)(g_es2 + (size_t)s_l * 4);
            w4.x = __expf(lrelu(a.x + edv.x));
            w4.y = __expf(lrelu(a.y + edv.y));
            w4.z = __expf(lrelu(a.z + edv.z));
            w4.w = __expf(lrelu(a.w + edv.w));
            den.x += w4.x; den.y += w4.y; den.z += w4.z; den.w += w4.w;
        }
        float wx = __shfl_sync(0xffffffffu, w4.x, sub);
        float wy = __shfl_sync(0xffffffffu, w4.y, sub);
        float wz = __shfl_sync(0xffffffffu, w4.z, sub);
        float ww = __shfl_sync(0xffffffffu, w4.w, sub);
        float w = p == 0 ? wx : p == 1 ? wy : p == 2 ? wz : ww;

        if (s >= 0) {
            float4 hv = *(const float4*)(g_h2 + (size_t)s * HC2 + p * 4);
            acc.x += w * hv.x; acc.y += w * hv.y;
            acc.z += w * hv.z; acc.w += w * hv.w;
        }
    }

    #pragma unroll
    for (int o = 4; o <= 16; o <<= 1) {
        acc.x += __shfl_xor_sync(0xffffffffu, acc.x, o);
        acc.y += __shfl_xor_sync(0xffffffffu, acc.y, o);
        acc.z += __shfl_xor_sync(0xffffffffu, acc.z, o);
        acc.w += __shfl_xor_sync(0xffffffffu, acc.w, o);
    }
    #pragma unroll
    for (int o = 1; o <= 4; o <<= 1) {
        den.x += __shfl_xor_sync(0xffffffffu, den.x, o);
        den.y += __shfl_xor_sync(0xffffffffu, den.y, o);
        den.z += __shfl_xor_sync(0xffffffffu, den.z, o);
        den.w += __shfl_xor_sync(0xffffffffu, den.w, o);
    }
    float dnx = __shfl_sync(0xffffffffu, den.x, 0);
    float dny = __shfl_sync(0xffffffffu, den.y, 0);
    float dnz = __shfl_sync(0xffffffffu, den.z, 0);
    float dnw = __shfl_sync(0xffffffffu, den.w, 0);

    if (lane < 4) {
        int g;
        if (g_is64) g = (int)((const long long*)batch)[d];
        else        g = ((const int*)batch)[d];
        float dh = p == 0 ? dnx : p == 1 ? dny : p == 2 ? dnz : dnw;
        float ih = 1.f / (dh + 1e-16f);
        float4 bb = *(const float4*)&sB2[p * 4];
        float o0 = fmaxf(acc.x * ih + bb.x, 0.f);
        float o1 = fmaxf(acc.y * ih + bb.y, 0.f);
        float o2 = fmaxf(acc.z * ih + bb.z, 0.f);
        float o3 = fmaxf(acc.w * ih + bb.w, 0.f);
        red4(g_pool + g * HC2 + p * 4, o0, o1, o2, o3);
        if (p == 0) atomicAdd(&g_cnt[g], 1.f);
    }
}

// ---------------- final ----------------
__global__ void final_kernel(const float* __restrict__ Wf, const float* __restrict__ bf,
                             float* __restrict__ out) {
    const int t = threadIdx.x;
    if (t >= N_GRAPHS * OUT_DIM) return;
    const int g = t / OUT_DIM;
    const int o = t % OUT_DIM;
    const float c = fmaxf(g_cnt[g], 1.f);
    float acc = bf[o];
    #pragma unroll
    for (int j = 0; j < HC2; j++)
        acc += (g_pool[g * HC2 + j] / c) * Wf[j * OUT_DIM + o];
    out[t] = acc;
}

// ---------------- stream/event holder ----------------
struct StreamHolder {
    cudaStream_t s2 = nullptr;
    cudaEvent_t  ev0 = nullptr, ev1 = nullptr;
    bool ok = false;
    StreamHolder() {
        if (cudaStreamCreateWithFlags(&s2, cudaStreamNonBlocking) != cudaSuccess) return;
        if (cudaEventCreateWithFlags(&ev0, cudaEventDisableTiming) != cudaSuccess) return;
        if (cudaEventCreateWithFlags(&ev1, cudaEventDisableTiming) != cudaSuccess) return;
        ok = true;
    }
};
static StreamHolder g_sh;

// ---------------- launch ----------------
extern "C" void kernel_launch(void* const* d_in, const int* in_sizes, int n_in,
                              void* d_out, int out_size) {
    const float* x       = (const float*)d_in[0];
    const void*  eidx    = d_in[1];
    const void*  batch   = d_in[2];
    const float* W1      = (const float*)d_in[3];
    const float* asrc1   = (const float*)d_in[4];
    const float* adst1   = (const float*)d_in[5];
    const float* b1      = (const float*)d_in[6];
    const float* W2      = (const float*)d_in[7];
    const float* asrc2   = (const float*)d_in[8];
    const float* adst2   = (const float*)d_in[9];
    const float* b2      = (const float*)d_in[10];
    const float* Wf      = (const float*)d_in[11];
    const float* bf      = (const float*)d_in[12];
    float* out = (float*)d_out;

    const int TB = 256;
    const int edgeGrid = (E_TOT + TB - 1) / TB;
    const int nodeGrid = (N_NODES + TB - 1) / TB;
    const int aggGrid  = (N_NODES * 32 + TB - 1) / TB;

    if (g_sh.ok) {
        init_kernel<<<nodeGrid, TB>>>();
        detect_kernel<<<1, 256>>>(eidx);
        cudaEventRecord(g_sh.ev0, 0);

        cudaStreamWaitEvent(g_sh.s2, g_sh.ev0, 0);
        count_kernel<<<edgeGrid, TB, 0, g_sh.s2>>>(eidx);
        scan1_kernel<<<N_SCAN_BLOCKS, SCAN_BS, 0, g_sh.s2>>>();
        scan2_kernel<<<1, 128, 0, g_sh.s2>>>();
        scan3_kernel<<<N_SCAN_BLOCKS, SCAN_BS, 0, g_sh.s2>>>();
        scatter_kernel<<<edgeGrid, TB, 0, g_sh.s2>>>(eidx);
        cudaEventRecord(g_sh.ev1, g_sh.s2);

        gemm1_kernel<<<(N_NODES + G1_BN - 1) / G1_BN, 128>>>(x, W1, asrc1, adst1);

        cudaStreamWaitEvent(0, g_sh.ev1, 0);
    } else {
        init_kernel<<<nodeGrid, TB>>>();
        detect_kernel<<<1, 256>>>(eidx);
        count_kernel<<<edgeGrid, TB>>>(eidx);
        scan1_kernel<<<N_SCAN_BLOCKS, SCAN_BS>>>();
        scan2_kernel<<<1, 128>>>();
        scan3_kernel<<<N_SCAN_BLOCKS, SCAN_BS>>>();
        scatter_kernel<<<edgeGrid, TB>>>(eidx);
        gemm1_kernel<<<(N_NODES + G1_BN - 1) / G1_BN, 128>>>(x, W1, asrc1, adst1);
    }

    agg1_kernel<<<aggGrid, TB>>>(b1, W2, asrc2, adst2);
    agg2_kernel<<<aggGrid, TB>>>(b2, batch);
    final_kernel<<<1, N_GRAPHS * OUT_DIM>>>(Wf, bf, out);
}

// round 8
// speedup vs baseline: 1.3254x; 1.3254x over previous
#include <cuda_runtime.h>
#include <cuda_bf16.h>

#define N_NODES   100000
#define N_EDGES   3200000
#define E_TOT     (N_EDGES + N_NODES)   // self loops appended
#define IN_DIM    512
#define HEADS     4
#define C1        8
#define C2        4
#define HC1       (HEADS*C1)   // 32
#define HC2       (HEADS*C2)   // 16
#define N_GRAPHS  64
#define OUT_DIM   10

#define SCAN_BS   1024
#define N_SCAN_BLOCKS ((N_NODES + SCAN_BS - 1) / SCAN_BS)   // 98

// ---------------- device scratch ----------------
__device__ __align__(16) float g_h1 [(size_t)N_NODES * HC1];
__device__ __align__(16) float g_es1[(size_t)N_NODES * HEADS];
__device__ __align__(16) float g_ed1[(size_t)N_NODES * HEADS];

__device__ __align__(16) float g_h2 [(size_t)N_NODES * HC2];
__device__ __align__(16) float g_es2[(size_t)N_NODES * HEADS];
__device__ __align__(16) float g_ed2[(size_t)N_NODES * HEADS];

__device__ __align__(16) float g_pool[N_GRAPHS * HC2];
__device__ float g_cnt [N_GRAPHS];

__device__ int g_deg[N_NODES];
__device__ int g_off[N_NODES + 1];
__device__ int g_pos[N_NODES];
__device__ int g_csr[E_TOT];
__device__ int g_blocksum[N_SCAN_BLOCKS];
__device__ int g_blockoff[N_SCAN_BLOCKS];

__device__ int g_is64;

// ---------------- helpers ----------------
__device__ __forceinline__ float lrelu(float v) { return v >= 0.f ? v : 0.2f * v; }

__device__ __forceinline__ void red4(float* p, float a, float b, float c, float d) {
    asm volatile("red.global.add.v4.f32 [%0], {%1,%2,%3,%4};"
                 :: "l"(p), "f"(a), "f"(b), "f"(c), "f"(d) : "memory");
}

__device__ __forceinline__ void load_edge(const void* ei, int i, int is64, int& s, int& d) {
    if (i < N_EDGES) {
        if (is64) {
            const long long* p = (const long long*)ei;
            s = (int)p[i];
            d = (int)p[(size_t)N_EDGES + i];
        } else {
            const int* p = (const int*)ei;
            s = p[i];
            d = p[(size_t)N_EDGES + i];
        }
    } else {
        s = d = i - N_EDGES;
    }
}

// ---------------- detect (parallel) + init ----------------
__global__ void detect_kernel(const void* ei) {
    const unsigned long long* p = (const unsigned long long*)ei;
    int big = (p[threadIdx.x] >= (unsigned long long)N_NODES) ? 1 : 0;
    unsigned any_big = __ballot_sync(0xffffffffu, big);
    __shared__ unsigned sb[8];
    if ((threadIdx.x & 31) == 0) sb[threadIdx.x >> 5] = any_big;
    __syncthreads();
    if (threadIdx.x == 0) {
        unsigned m = 0;
        #pragma unroll
        for (int i = 0; i < 8; i++) m |= sb[i];
        g_is64 = (m == 0) ? 1 : 0;
    }
}

__global__ void init_kernel() {
    int t = blockIdx.x * blockDim.x + threadIdx.x;
    if (t < N_NODES) g_deg[t] = 0;
    if (t < N_GRAPHS * HC2) g_pool[t] = 0.f;
    if (t < N_GRAPHS)       g_cnt[t]  = 0.f;
}

// ---------------- CSR build ----------------
__global__ void count_kernel(const void* __restrict__ ei) {
    int i = blockIdx.x * blockDim.x + threadIdx.x;
    if (i >= E_TOT) return;
    int d;
    if (i < N_EDGES) {
        if (g_is64) d = (int)((const long long*)ei)[(size_t)N_EDGES + i];
        else        d = ((const int*)ei)[(size_t)N_EDGES + i];
    } else {
        d = i - N_EDGES;
    }
    atomicAdd(&g_deg[d], 1);
}

__global__ void scan1_kernel() {
    __shared__ int sm[SCAN_BS];
    const int t = threadIdx.x;
    const int idx = blockIdx.x * SCAN_BS + t;
    int v = (idx < N_NODES) ? g_deg[idx] : 0;
    sm[t] = v;
    __syncthreads();
    #pragma unroll
    for (int off = 1; off < SCAN_BS; off <<= 1) {
        int u = (t >= off) ? sm[t - off] : 0;
        __syncthreads();
        sm[t] += u;
        __syncthreads();
    }
    if (idx < N_NODES) g_off[idx] = sm[t] - v;
    if (t == SCAN_BS - 1) g_blocksum[blockIdx.x] = sm[t];
}

__global__ void scan2_kernel() {
    __shared__ int sm[128];
    const int t = threadIdx.x;
    int v = (t < N_SCAN_BLOCKS) ? g_blocksum[t] : 0;
    sm[t] = v;
    __syncthreads();
    #pragma unroll
    for (int off = 1; off < 128; off <<= 1) {
        int u = (t >= off) ? sm[t - off] : 0;
        __syncthreads();
        sm[t] += u;
        __syncthreads();
    }
    if (t < N_SCAN_BLOCKS) g_blockoff[t] = sm[t] - v;
}

__global__ void scan3_kernel() {
    const int idx = blockIdx.x * blockDim.x + threadIdx.x;
    if (idx < N_NODES) {
        int o = g_off[idx] + g_blockoff[blockIdx.x];
        g_off[idx] = o;
        g_pos[idx] = o;
    }
    if (idx == 0) g_off[N_NODES] = E_TOT;
}

__global__ void scatter_kernel(const void* __restrict__ ei) {
    int i = blockIdx.x * blockDim.x + threadIdx.x;
    if (i >= E_TOT) return;
    int s, d;
    load_edge(ei, i, g_is64, s, d);
    int p = atomicAdd(&g_pos[d], 1);
    g_csr[p] = s;
}

// ---------------- gemm1: h1 = x @ W1 (512->32), 8x8 register tile (R6) -------
#define G1_BN 256
#define G1_BK 32
__global__ __launch_bounds__(128) void gemm1_kernel(const float* __restrict__ x,
                                                    const float* __restrict__ W1,
                                                    const float* __restrict__ a_src,
                                                    const float* __restrict__ a_dst) {
    __shared__ float sX[G1_BN][36];
    __shared__ float sW[G1_BK][36];
    const int tid = threadIdx.x;
    const int nbase = blockIdx.x * G1_BN;
    const int ng = tid >> 2;
    const int cg = tid & 3;
    const int c0 = cg * 8;

    float4 acc[8][2];
    #pragma unroll
    for (int j = 0; j < 8; j++) { acc[j][0] = make_float4(0,0,0,0); acc[j][1] = make_float4(0,0,0,0); }

    for (int k0 = 0; k0 < IN_DIM; k0 += G1_BK) {
        __syncthreads();
        for (int i = tid; i < G1_BN * (G1_BK / 4); i += 128) {
            int n = i >> 3, kv = i & 7;
            float4 v = make_float4(0,0,0,0);
            if (nbase + n < N_NODES)
                v = *(const float4*)(x + (size_t)(nbase + n) * IN_DIM + k0 + kv * 4);
            *(float4*)&sX[n][kv * 4] = v;
        }
        for (int i = tid; i < G1_BK * 32; i += 128) {
            int k = i >> 5, c = i & 31;
            sW[k][c] = W1[(size_t)(k0 + k) * 32 + c];
        }
        __syncthreads();
        #pragma unroll
        for (int k4 = 0; k4 < G1_BK; k4 += 4) {
            float4 xt[8];
            #pragma unroll
            for (int j = 0; j < 8; j++) xt[j] = *(const float4*)&sX[ng + j * 32][k4];
            #pragma unroll
            for (int kk = 0; kk < 4; kk++) {
                float4 w0 = *(const float4*)&sW[k4 + kk][c0];
                float4 w1 = *(const float4*)&sW[k4 + kk][c0 + 4];
                #pragma unroll
                for (int j = 0; j < 8; j++) {
                    float xv = (kk == 0) ? xt[j].x : (kk == 1) ? xt[j].y : (kk == 2) ? xt[j].z : xt[j].w;
                    acc[j][0].x += xv * w0.x; acc[j][0].y += xv * w0.y;
                    acc[j][0].z += xv * w0.z; acc[j][0].w += xv * w0.w;
                    acc[j][1].x += xv * w1.x; acc[j][1].y += xv * w1.y;
                    acc[j][1].z += xv * w1.z; acc[j][1].w += xv * w1.w;
                }
            }
        }
    }

    float as0 = a_src[c0+0], as1 = a_src[c0+1], as2 = a_src[c0+2], as3 = a_src[c0+3];
    float as4 = a_src[c0+4], as5 = a_src[c0+5], as6 = a_src[c0+6], as7 = a_src[c0+7];
    float ad0 = a_dst[c0+0], ad1 = a_dst[c0+1], ad2 = a_dst[c0+2], ad3 = a_dst[c0+3];
    float ad4 = a_dst[c0+4], ad5 = a_dst[c0+5], ad6 = a_dst[c0+6], ad7 = a_dst[c0+7];
    #pragma unroll
    for (int j = 0; j < 8; j++) {
        int n = nbase + ng + j * 32;
        if (n >= N_NODES) continue;
        *(float4*)&g_h1[(size_t)n * HC1 + c0]     = acc[j][0];
        *(float4*)&g_h1[(size_t)n * HC1 + c0 + 4] = acc[j][1];
        float es = acc[j][0].x*as0 + acc[j][0].y*as1 + acc[j][0].z*as2 + acc[j][0].w*as3
                 + acc[j][1].x*as4 + acc[j][1].y*as5 + acc[j][1].z*as6 + acc[j][1].w*as7;
        float ed = acc[j][0].x*ad0 + acc[j][0].y*ad1 + acc[j][0].z*ad2 + acc[j][0].w*ad3
                 + acc[j][1].x*ad4 + acc[j][1].y*ad5 + acc[j][1].z*ad6 + acc[j][1].w*ad7;
        g_es1[(size_t)n * HEADS + cg] = es;
        g_ed1[(size_t)n * HEADS + cg] = ed;
    }
}

// ---------------- agg1: pipelined coalesced aggregation + fused gemm2 --------
// Software pipeline depth 1: csr indices + es gathers for iteration it+1 are
// issued while iteration it computes, removing 2 of 3 L2 round-trips from the
// exposed dependency chain.
__global__ __launch_bounds__(256) void agg1_kernel(const float* __restrict__ b1,
                                                   const float* __restrict__ W2,
                                                   const float* __restrict__ a_src2,
                                                   const float* __restrict__ a_dst2) {
    __shared__ float sW2[HC1 * HC2];
    __shared__ __align__(16) float sB1[HC1];
    __shared__ float sA2s[HC2], sA2d[HC2];
    {
        const int t = threadIdx.x;
        for (int i = t; i < HC1 * HC2; i += 256) sW2[i] = W2[i];
        if (t < HC1) sB1[t] = b1[t];
        if (t < HC2) { sA2s[t] = a_src2[t]; sA2d[t] = a_dst2[t]; }
        __syncthreads();
    }

    const int warp = (blockIdx.x * blockDim.x + threadIdx.x) >> 5;
    if (warp >= N_NODES) return;
    const int lane = threadIdx.x & 31;
    const int d    = warp;
    const int beg  = g_off[d];
    const int end  = g_off[d + 1];
    const int e    = lane >> 3;
    const int p    = lane & 7;
    const int head = p >> 1;
    const float4 edv = *(const float4*)(g_ed1 + (size_t)d * 4);

    float4 den = make_float4(0,0,0,0);
    float4 acc = make_float4(0,0,0,0);

    // prologue prefetch (iteration 0)
    int   s_pf = -1;
    float4 a_pf = make_float4(0,0,0,0);
    if (lane < 4 && beg + lane < end) s_pf = g_csr[beg + lane];
    if (s_pf >= 0) a_pf = *(const float4*)(g_es1 + (size_t)s_pf * 4);

    const int iters = (end - beg + 3) >> 2;
    for (int it = 0; it < iters; ++it) {
        const int s_l = s_pf;
        const float4 a = a_pf;

        // issue next iteration's prefetch immediately
        const int nb = beg + (it + 1) * 4;
        s_pf = -1;
        if (lane < 4 && nb + lane < end) s_pf = g_csr[nb + lane];
        if (s_pf >= 0) a_pf = *(const float4*)(g_es1 + (size_t)s_pf * 4);

        const int s = __shfl_sync(0xffffffffu, s_l, e);

        float4 w4 = make_float4(0,0,0,0);
        if (lane < 4 && s_l >= 0) {
            w4.x = __expf(lrelu(a.x + edv.x));
            w4.y = __expf(lrelu(a.y + edv.y));
            w4.z = __expf(lrelu(a.z + edv.z));
            w4.w = __expf(lrelu(a.w + edv.w));
            den.x += w4.x; den.y += w4.y; den.z += w4.z; den.w += w4.w;
        }
        float wx = __shfl_sync(0xffffffffu, w4.x, e);
        float wy = __shfl_sync(0xffffffffu, w4.y, e);
        float wz = __shfl_sync(0xffffffffu, w4.z, e);
        float ww = __shfl_sync(0xffffffffu, w4.w, e);
        float w = head == 0 ? wx : head == 1 ? wy : head == 2 ? wz : ww;

        if (s >= 0) {
            float4 hv = *(const float4*)(g_h1 + (size_t)s * HC1 + p * 4);
            acc.x += w * hv.x; acc.y += w * hv.y;
            acc.z += w * hv.z; acc.w += w * hv.w;
        }
    }

    #pragma unroll
    for (int o = 8; o <= 16; o <<= 1) {
        acc.x += __shfl_xor_sync(0xffffffffu, acc.x, o);
        acc.y += __shfl_xor_sync(0xffffffffu, acc.y, o);
        acc.z += __shfl_xor_sync(0xffffffffu, acc.z, o);
        acc.w += __shfl_xor_sync(0xffffffffu, acc.w, o);
    }
    #pragma unroll
    for (int o = 1; o <= 2; o <<= 1) {
        den.x += __shfl_xor_sync(0xffffffffu, den.x, o);
        den.y += __shfl_xor_sync(0xffffffffu, den.y, o);
        den.z += __shfl_xor_sync(0xffffffffu, den.z, o);
        den.w += __shfl_xor_sync(0xffffffffu, den.w, o);
    }
    float dnx = __shfl_sync(0xffffffffu, den.x, 0);
    float dny = __shfl_sync(0xffffffffu, den.y, 0);
    float dnz = __shfl_sync(0xffffffffu, den.z, 0);
    float dnw = __shfl_sync(0xffffffffu, den.w, 0);
    float dh  = head == 0 ? dnx : head == 1 ? dny : head == 2 ? dnz : dnw;
    float ih  = 1.f / (dh + 1e-16f);

    float4 bb = *(const float4*)&sB1[p * 4];
    float r0 = fmaxf(acc.x * ih + bb.x, 0.f);
    float r1 = fmaxf(acc.y * ih + bb.y, 0.f);
    float r2 = fmaxf(acc.z * ih + bb.z, 0.f);
    float r3 = fmaxf(acc.w * ih + bb.w, 0.f);

    const int k0 = p * 4, c0 = e * 4;
    float4 pc = make_float4(0,0,0,0);
    #pragma unroll
    for (int kk = 0; kk < 4; kk++) {
        float rv = kk == 0 ? r0 : kk == 1 ? r1 : kk == 2 ? r2 : r3;
        const float* wrow = &sW2[(k0 + kk) * HC2 + c0];
        pc.x += rv * wrow[0]; pc.y += rv * wrow[1];
        pc.z += rv * wrow[2]; pc.w += rv * wrow[3];
    }
    #pragma unroll
    for (int o = 1; o <= 4; o <<= 1) {
        pc.x += __shfl_xor_sync(0xffffffffu, pc.x, o);
        pc.y += __shfl_xor_sync(0xffffffffu, pc.y, o);
        pc.z += __shfl_xor_sync(0xffffffffu, pc.z, o);
        pc.w += __shfl_xor_sync(0xffffffffu, pc.w, o);
    }
    if (p == 0) {
        *(float4*)&g_h2[(size_t)d * HC2 + c0] = pc;
        float es = pc.x * sA2s[c0] + pc.y * sA2s[c0+1] + pc.z * sA2s[c0+2] + pc.w * sA2s[c0+3];
        float ed = pc.x * sA2d[c0] + pc.y * sA2d[c0+1] + pc.z * sA2d[c0+2] + pc.w * sA2d[c0+3];
        g_es2[(size_t)d * HEADS + e] = es;
        g_ed2[(size_t)d * HEADS + e] = ed;
    }
}

// ---------------- agg2: pipelined coalesced aggregation + fused relu+pool ----
__global__ __launch_bounds__(256) void agg2_kernel(const float* __restrict__ b2,
                                                   const void* __restrict__ batch) {
    __shared__ __align__(16) float sB2[HC2];
    if (threadIdx.x < HC2) sB2[threadIdx.x] = b2[threadIdx.x];
    __syncthreads();

    const int warp = (blockIdx.x * blockDim.x + threadIdx.x) >> 5;
    if (warp >= N_NODES) return;
    const int lane = threadIdx.x & 31;
    const int d    = warp;
    const int beg  = g_off[d];
    const int end  = g_off[d + 1];
    const int sub  = lane >> 2;
    const int p    = lane & 3;
    const float4 edv = *(const float4*)(g_ed2 + (size_t)d * 4);

    float4 den = make_float4(0,0,0,0);
    float4 acc = make_float4(0,0,0,0);

    int   s_pf = -1;
    float4 a_pf = make_float4(0,0,0,0);
    if (lane < 8 && beg + lane < end) s_pf = g_csr[beg + lane];
    if (s_pf >= 0) a_pf = *(const float4*)(g_es2 + (size_t)s_pf * 4);

    const int iters = (end - beg + 7) >> 3;
    for (int it = 0; it < iters; ++it) {
        const int s_l = s_pf;
        const float4 a = a_pf;

        const int nb = beg + (it + 1) * 8;
        s_pf = -1;
        if (lane < 8 && nb + lane < end) s_pf = g_csr[nb + lane];
        if (s_pf >= 0) a_pf = *(const float4*)(g_es2 + (size_t)s_pf * 4);

        const int s = __shfl_sync(0xffffffffu, s_l, sub);

        float4 w4 = make_float4(0,0,0,0);
        if (lane < 8 && s_l >= 0) {
            w4.x = __expf(lrelu(a.x + edv.x));
            w4.y = __expf(lrelu(a.y + edv.y));
            w4.z = __expf(lrelu(a.z + edv.z));
            w4.w = __expf(lrelu(a.w + edv.w));
            den.x += w4.x; den.y += w4.y; den.z += w4.z; den.w += w4.w;
        }
        float wx = __shfl_sync(0xffffffffu, w4.x, sub);
        float wy = __shfl_sync(0xffffffffu, w4.y, sub);
        float wz = __shfl_sync(0xffffffffu, w4.z, sub);
        float ww = __shfl_sync(0xffffffffu, w4.w, sub);
        float w = p == 0 ? wx : p == 1 ? wy : p == 2 ? wz : ww;

        if (s >= 0) {
            float4 hv = *(const float4*)(g_h2 + (size_t)s * HC2 + p * 4);
            acc.x += w * hv.x; acc.y += w * hv.y;
            acc.z += w * hv.z; acc.w += w * hv.w;
        }
    }

    #pragma unroll
    for (int o = 4; o <= 16; o <<= 1) {
        acc.x += __shfl_xor_sync(0xffffffffu, acc.x, o);
        acc.y += __shfl_xor_sync(0xffffffffu, acc.y, o);
        acc.z += __shfl_xor_sync(0xffffffffu, acc.z, o);
        acc.w += __shfl_xor_sync(0xffffffffu, acc.w, o);
    }
    #pragma unroll
    for (int o = 1; o <= 4; o <<= 1) {
        den.x += __shfl_xor_sync(0xffffffffu, den.x, o);
        den.y += __shfl_xor_sync(0xffffffffu, den.y, o);
        den.z += __shfl_xor_sync(0xffffffffu, den.z, o);
        den.w += __shfl_xor_sync(0xffffffffu, den.w, o);
    }
    float dnx = __shfl_sync(0xffffffffu, den.x, 0);
    float dny = __shfl_sync(0xffffffffu, den.y, 0);
    float dnz = __shfl_sync(0xffffffffu, den.z, 0);
    float dnw = __shfl_sync(0xffffffffu, den.w, 0);

    if (lane < 4) {
        int g;
        if (g_is64) g = (int)((const long long*)batch)[d];
        else        g = ((const int*)batch)[d];
        float dh = p == 0 ? dnx : p == 1 ? dny : p == 2 ? dnz : dnw;
        float ih = 1.f / (dh + 1e-16f);
        float4 bb = *(const float4*)&sB2[p * 4];
        float o0 = fmaxf(acc.x * ih + bb.x, 0.f);
        float o1 = fmaxf(acc.y * ih + bb.y, 0.f);
        float o2 = fmaxf(acc.z * ih + bb.z, 0.f);
        float o3 = fmaxf(acc.w * ih + bb.w, 0.f);
        red4(g_pool + g * HC2 + p * 4, o0, o1, o2, o3);
        if (p == 0) atomicAdd(&g_cnt[g], 1.f);
    }
}

// ---------------- final ----------------
__global__ void final_kernel(const float* __restrict__ Wf, const float* __restrict__ bf,
                             float* __restrict__ out) {
    const int t = threadIdx.x;
    if (t >= N_GRAPHS * OUT_DIM) return;
    const int g = t / OUT_DIM;
    const int o = t % OUT_DIM;
    const float c = fmaxf(g_cnt[g], 1.f);
    float acc = bf[o];
    #pragma unroll
    for (int j = 0; j < HC2; j++)
        acc += (g_pool[g * HC2 + j] / c) * Wf[j * OUT_DIM + o];
    out[t] = acc;
}

// ---------------- stream/event holder ----------------
struct StreamHolder {
    cudaStream_t s2 = nullptr;
    cudaEvent_t  ev0 = nullptr, ev1 = nullptr;
    bool ok = false;
    StreamHolder() {
        if (cudaStreamCreateWithFlags(&s2, cudaStreamNonBlocking) != cudaSuccess) return;
        if (cudaEventCreateWithFlags(&ev0, cudaEventDisableTiming) != cudaSuccess) return;
        if (cudaEventCreateWithFlags(&ev1, cudaEventDisableTiming) != cudaSuccess) return;
        ok = true;
    }
};
static StreamHolder g_sh;

// ---------------- launch ----------------
extern "C" void kernel_launch(void* const* d_in, const int* in_sizes, int n_in,
                              void* d_out, int out_size) {
    const float* x       = (const float*)d_in[0];
    const void*  eidx    = d_in[1];
    const void*  batch   = d_in[2];
    const float* W1      = (const float*)d_in[3];
    const float* asrc1   = (const float*)d_in[4];
    const float* adst1   = (const float*)d_in[5];
    const float* b1      = (const float*)d_in[6];
    const float* W2      = (const float*)d_in[7];
    const float* asrc2   = (const float*)d_in[8];
    const float* adst2   = (const float*)d_in[9];
    const float* b2      = (const float*)d_in[10];
    const float* Wf      = (const float*)d_in[11];
    const float* bf      = (const float*)d_in[12];
    float* out = (float*)d_out;

    const int TB = 256;
    const int edgeGrid = (E_TOT + TB - 1) / TB;
    const int nodeGrid = (N_NODES + TB - 1) / TB;
    const int aggGrid  = (N_NODES * 32 + TB - 1) / TB;

    if (g_sh.ok) {
        init_kernel<<<nodeGrid, TB>>>();
        detect_kernel<<<1, 256>>>(eidx);
        cudaEventRecord(g_sh.ev0, 0);

        cudaStreamWaitEvent(g_sh.s2, g_sh.ev0, 0);
        count_kernel<<<edgeGrid, TB, 0, g_sh.s2>>>(eidx);
        scan1_kernel<<<N_SCAN_BLOCKS, SCAN_BS, 0, g_sh.s2>>>();
        scan2_kernel<<<1, 128, 0, g_sh.s2>>>();
        scan3_kernel<<<N_SCAN_BLOCKS, SCAN_BS, 0, g_sh.s2>>>();
        scatter_kernel<<<edgeGrid, TB, 0, g_sh.s2>>>(eidx);
        cudaEventRecord(g_sh.ev1, g_sh.s2);

        gemm1_kernel<<<(N_NODES + G1_BN - 1) / G1_BN, 128>>>(x, W1, asrc1, adst1);

        cudaStreamWaitEvent(0, g_sh.ev1, 0);
    } else {
        init_kernel<<<nodeGrid, TB>>>();
        detect_kernel<<<1, 256>>>(eidx);
        count_kernel<<<edgeGrid, TB>>>(eidx);
        scan1_kernel<<<N_SCAN_BLOCKS, SCAN_BS>>>();
        scan2_kernel<<<1, 128>>>();
        scan3_kernel<<<N_SCAN_BLOCKS, SCAN_BS>>>();
        scatter_kernel<<<edgeGrid, TB>>>(eidx);
        gemm1_kernel<<<(N_NODES + G1_BN - 1) / G1_BN, 128>>>(x, W1, asrc1, adst1);
    }

    agg1_kernel<<<aggGrid, TB>>>(b1, W2, asrc2, adst2);
    agg2_kernel<<<aggGrid, TB>>>(b2, batch);
    final_kernel<<<1, N_GRAPHS * OUT_DIM>>>(Wf, bf, out);
}

// round 9
// speedup vs baseline: 1.5479x; 1.1678x over previous
#include <cuda_runtime.h>
#include <cuda_bf16.h>

#define N_NODES   100000
#define N_EDGES   3200000
#define E_TOT     (N_EDGES + N_NODES)   // self loops appended
#define IN_DIM    512
#define HEADS     4
#define C1        8
#define C2        4
#define HC1       (HEADS*C1)   // 32
#define HC2       (HEADS*C2)   // 16
#define N_GRAPHS  64
#define OUT_DIM   10

#define SCAN_BS   1024
#define N_SCAN_BLOCKS ((N_NODES + SCAN_BS - 1) / SCAN_BS)   // 98

// ---------------- device scratch ----------------
__device__ __align__(16) float g_h1 [(size_t)N_NODES * HC1];
__device__ __align__(16) float g_es1[(size_t)N_NODES * HEADS];
__device__ __align__(16) float g_ed1[(size_t)N_NODES * HEADS];

__device__ __align__(16) float g_h2 [(size_t)N_NODES * HC2];
__device__ __align__(16) float g_es2[(size_t)N_NODES * HEADS];
__device__ __align__(16) float g_ed2[(size_t)N_NODES * HEADS];

__device__ __align__(16) float g_pool[N_GRAPHS * HC2];
__device__ float g_cnt [N_GRAPHS];

__device__ int g_deg[N_NODES];
__device__ int g_off[N_NODES + 1];
__device__ int g_pos[N_NODES];
__device__ int g_csr[E_TOT];
__device__ int g_blocksum[N_SCAN_BLOCKS];
__device__ int g_blockoff[N_SCAN_BLOCKS];

__device__ int g_is64;

// ---------------- helpers ----------------
__device__ __forceinline__ float lrelu(float v) { return v >= 0.f ? v : 0.2f * v; }

__device__ __forceinline__ void red4(float* p, float a, float b, float c, float d) {
    asm volatile("red.global.add.v4.f32 [%0], {%1,%2,%3,%4};"
                 :: "l"(p), "f"(a), "f"(b), "f"(c), "f"(d) : "memory");
}

__device__ __forceinline__ void load_edge(const void* ei, int i, int is64, int& s, int& d) {
    if (i < N_EDGES) {
        if (is64) {
            const long long* p = (const long long*)ei;
            s = (int)p[i];
            d = (int)p[(size_t)N_EDGES + i];
        } else {
            const int* p = (const int*)ei;
            s = p[i];
            d = p[(size_t)N_EDGES + i];
        }
    } else {
        s = d = i - N_EDGES;
    }
}

// ---------------- detect (parallel) + init ----------------
__global__ void detect_kernel(const void* ei) {
    const unsigned long long* p = (const unsigned long long*)ei;
    int big = (p[threadIdx.x] >= (unsigned long long)N_NODES) ? 1 : 0;
    unsigned any_big = __ballot_sync(0xffffffffu, big);
    __shared__ unsigned sb[8];
    if ((threadIdx.x & 31) == 0) sb[threadIdx.x >> 5] = any_big;
    __syncthreads();
    if (threadIdx.x == 0) {
        unsigned m = 0;
        #pragma unroll
        for (int i = 0; i < 8; i++) m |= sb[i];
        g_is64 = (m == 0) ? 1 : 0;
    }
}

__global__ void init_kernel() {
    int t = blockIdx.x * blockDim.x + threadIdx.x;
    if (t < N_NODES) g_deg[t] = 0;
    if (t < N_GRAPHS * HC2) g_pool[t] = 0.f;
    if (t < N_GRAPHS)       g_cnt[t]  = 0.f;
}

// ---------------- CSR build ----------------
__global__ void count_kernel(const void* __restrict__ ei) {
    int i = blockIdx.x * blockDim.x + threadIdx.x;
    if (i >= E_TOT) return;
    int d;
    if (i < N_EDGES) {
        if (g_is64) d = (int)((const long long*)ei)[(size_t)N_EDGES + i];
        else        d = ((const int*)ei)[(size_t)N_EDGES + i];
    } else {
        d = i - N_EDGES;
    }
    atomicAdd(&g_deg[d], 1);
}

__global__ void scan1_kernel() {
    __shared__ int sm[SCAN_BS];
    const int t = threadIdx.x;
    const int idx = blockIdx.x * SCAN_BS + t;
    int v = (idx < N_NODES) ? g_deg[idx] : 0;
    sm[t] = v;
    __syncthreads();
    #pragma unroll
    for (int off = 1; off < SCAN_BS; off <<= 1) {
        int u = (t >= off) ? sm[t - off] : 0;
        __syncthreads();
        sm[t] += u;
        __syncthreads();
    }
    if (idx < N_NODES) g_off[idx] = sm[t] - v;
    if (t == SCAN_BS - 1) g_blocksum[blockIdx.x] = sm[t];
}

__global__ void scan2_kernel() {
    __shared__ int sm[128];
    const int t = threadIdx.x;
    int v = (t < N_SCAN_BLOCKS) ? g_blocksum[t] : 0;
    sm[t] = v;
    __syncthreads();
    #pragma unroll
    for (int off = 1; off < 128; off <<= 1) {
        int u = (t >= off) ? sm[t - off] : 0;
        __syncthreads();
        sm[t] += u;
        __syncthreads();
    }
    if (t < N_SCAN_BLOCKS) g_blockoff[t] = sm[t] - v;
}

__global__ void scan3_kernel() {
    const int idx = blockIdx.x * blockDim.x + threadIdx.x;
    if (idx < N_NODES) {
        int o = g_off[idx] + g_blockoff[blockIdx.x];
        g_off[idx] = o;
        g_pos[idx] = o;
    }
    if (idx == 0) g_off[N_NODES] = E_TOT;
}

__global__ void scatter_kernel(const void* __restrict__ ei) {
    int i = blockIdx.x * blockDim.x + threadIdx.x;
    if (i >= E_TOT) return;
    int s, d;
    load_edge(ei, i, g_is64, s, d);
    int p = atomicAdd(&g_pos[d], 1);
    g_csr[p] = s;
}

// ---------------- gemm1: h1 = x @ W1 (512->32), 8x8 register tile (R6) -------
#define G1_BN 256
#define G1_BK 32
__global__ __launch_bounds__(128) void gemm1_kernel(const float* __restrict__ x,
                                                    const float* __restrict__ W1,
                                                    const float* __restrict__ a_src,
                                                    const float* __restrict__ a_dst) {
    __shared__ float sX[G1_BN][36];
    __shared__ float sW[G1_BK][36];
    const int tid = threadIdx.x;
    const int nbase = blockIdx.x * G1_BN;
    const int ng = tid >> 2;
    const int cg = tid & 3;
    const int c0 = cg * 8;

    float4 acc[8][2];
    #pragma unroll
    for (int j = 0; j < 8; j++) { acc[j][0] = make_float4(0,0,0,0); acc[j][1] = make_float4(0,0,0,0); }

    for (int k0 = 0; k0 < IN_DIM; k0 += G1_BK) {
        __syncthreads();
        for (int i = tid; i < G1_BN * (G1_BK / 4); i += 128) {
            int n = i >> 3, kv = i & 7;
            float4 v = make_float4(0,0,0,0);
            if (nbase + n < N_NODES)
                v = *(const float4*)(x + (size_t)(nbase + n) * IN_DIM + k0 + kv * 4);
            *(float4*)&sX[n][kv * 4] = v;
        }
        for (int i = tid; i < G1_BK * 32; i += 128) {
            int k = i >> 5, c = i & 31;
            sW[k][c] = W1[(size_t)(k0 + k) * 32 + c];
        }
        __syncthreads();
        #pragma unroll
        for (int k4 = 0; k4 < G1_BK; k4 += 4) {
            float4 xt[8];
            #pragma unroll
            for (int j = 0; j < 8; j++) xt[j] = *(const float4*)&sX[ng + j * 32][k4];
            #pragma unroll
            for (int kk = 0; kk < 4; kk++) {
                float4 w0 = *(const float4*)&sW[k4 + kk][c0];
                float4 w1 = *(const float4*)&sW[k4 + kk][c0 + 4];
                #pragma unroll
                for (int j = 0; j < 8; j++) {
                    float xv = (kk == 0) ? xt[j].x : (kk == 1) ? xt[j].y : (kk == 2) ? xt[j].z : xt[j].w;
                    acc[j][0].x += xv * w0.x; acc[j][0].y += xv * w0.y;
                    acc[j][0].z += xv * w0.z; acc[j][0].w += xv * w0.w;
                    acc[j][1].x += xv * w1.x; acc[j][1].y += xv * w1.y;
                    acc[j][1].z += xv * w1.z; acc[j][1].w += xv * w1.w;
                }
            }
        }
    }

    float as0 = a_src[c0+0], as1 = a_src[c0+1], as2 = a_src[c0+2], as3 = a_src[c0+3];
    float as4 = a_src[c0+4], as5 = a_src[c0+5], as6 = a_src[c0+6], as7 = a_src[c0+7];
    float ad0 = a_dst[c0+0], ad1 = a_dst[c0+1], ad2 = a_dst[c0+2], ad3 = a_dst[c0+3];
    float ad4 = a_dst[c0+4], ad5 = a_dst[c0+5], ad6 = a_dst[c0+6], ad7 = a_dst[c0+7];
    #pragma unroll
    for (int j = 0; j < 8; j++) {
        int n = nbase + ng + j * 32;
        if (n >= N_NODES) continue;
        *(float4*)&g_h1[(size_t)n * HC1 + c0]     = acc[j][0];
        *(float4*)&g_h1[(size_t)n * HC1 + c0 + 4] = acc[j][1];
        float es = acc[j][0].x*as0 + acc[j][0].y*as1 + acc[j][0].z*as2 + acc[j][0].w*as3
                 + acc[j][1].x*as4 + acc[j][1].y*as5 + acc[j][1].z*as6 + acc[j][1].w*as7;
        float ed = acc[j][0].x*ad0 + acc[j][0].y*ad1 + acc[j][0].z*ad2 + acc[j][0].w*ad3
                 + acc[j][1].x*ad4 + acc[j][1].y*ad5 + acc[j][1].z*ad6 + acc[j][1].w*ad7;
        g_es1[(size_t)n * HEADS + cg] = es;
        g_ed1[(size_t)n * HEADS + cg] = ed;
    }
}

// ---------------- agg1: full-lane aggregation + fused gemm2 + scores2 --------
// Exp phase: 32 lanes = 8 edges x 4 heads (one exp per lane).
// Gather phase: two halves of 4 edges x 8 parts; weight fetched with one shfl.
__global__ __launch_bounds__(256) void agg1_kernel(const float* __restrict__ b1,
                                                   const float* __restrict__ W2,
                                                   const float* __restrict__ a_src2,
                                                   const float* __restrict__ a_dst2) {
    __shared__ float sW2[HC1 * HC2];
    __shared__ __align__(16) float sB1[HC1];
    __shared__ float sA2s[HC2], sA2d[HC2];
    {
        const int t = threadIdx.x;
        for (int i = t; i < HC1 * HC2; i += 256) sW2[i] = W2[i];
        if (t < HC1) sB1[t] = b1[t];
        if (t < HC2) { sA2s[t] = a_src2[t]; sA2d[t] = a_dst2[t]; }
        __syncthreads();
    }

    const int warp = (blockIdx.x * blockDim.x + threadIdx.x) >> 5;
    if (warp >= N_NODES) return;
    const int lane = threadIdx.x & 31;
    const int d    = warp;
    const int beg  = g_off[d];
    const int end  = g_off[d + 1];
    const int le = lane >> 2, lh = lane & 3;   // exp phase: edge slot, head
    const int e  = lane >> 3, p = lane & 7;    // gather phase: edge-in-half, part
    const int hp = p >> 1;                     // head of part p

    const float edv_s = g_ed1[(size_t)d * 4 + lh];

    float  den_l = 0.f;
    float4 acc = make_float4(0,0,0,0);

    for (int base = beg; base < end; base += 8) {
        const int idx = base + le;
        int s_e = -1; float w = 0.f;
        if (idx < end) {
            s_e = g_csr[idx];
            float es_s = g_es1[(size_t)s_e * 4 + lh];
            w = __expf(lrelu(es_s + edv_s));
            den_l += w;
        }
        #pragma unroll
        for (int j = 0; j < 2; j++) {
            const int he = e + j * 4;                            // edge slot 0..7
            const int s_h = __shfl_sync(0xffffffffu, s_e, he * 4);
            const float w_h = __shfl_sync(0xffffffffu, w, he * 4 + hp);
            if (s_h >= 0) {
                float4 hv = *(const float4*)(g_h1 + (size_t)s_h * HC1 + p * 4);
                acc.x += w_h * hv.x; acc.y += w_h * hv.y;
                acc.z += w_h * hv.z; acc.w += w_h * hv.w;
            }
        }
    }

    // acc: reduce over lanes with same p (xor 8, 16)
    #pragma unroll
    for (int o = 8; o <= 16; o <<= 1) {
        acc.x += __shfl_xor_sync(0xffffffffu, acc.x, o);
        acc.y += __shfl_xor_sync(0xffffffffu, acc.y, o);
        acc.z += __shfl_xor_sync(0xffffffffu, acc.z, o);
        acc.w += __shfl_xor_sync(0xffffffffu, acc.w, o);
    }
    // den: reduce over edge slots (xor 4, 8, 16) -> every lane holds den[its lh]
    #pragma unroll
    for (int o = 4; o <= 16; o <<= 1)
        den_l += __shfl_xor_sync(0xffffffffu, den_l, o);
    const float den_h = __shfl_sync(0xffffffffu, den_l, hp);  // den for head of part p
    const float ih = 1.f / (den_h + 1e-16f);

    float4 bb = *(const float4*)&sB1[p * 4];
    float r0 = fmaxf(acc.x * ih + bb.x, 0.f);
    float r1 = fmaxf(acc.y * ih + bb.y, 0.f);
    float r2 = fmaxf(acc.z * ih + bb.z, 0.f);
    float r3 = fmaxf(acc.w * ih + bb.w, 0.f);

    // fused gemm2: lane computes partials for h2 cols e*4..e*4+3 over k = p*4..p*4+3
    const int k0 = p * 4, c0 = e * 4;
    float4 pc = make_float4(0,0,0,0);
    #pragma unroll
    for (int kk = 0; kk < 4; kk++) {
        float rv = kk == 0 ? r0 : kk == 1 ? r1 : kk == 2 ? r2 : r3;
        const float* wrow = &sW2[(k0 + kk) * HC2 + c0];
        pc.x += rv * wrow[0]; pc.y += rv * wrow[1];
        pc.z += rv * wrow[2]; pc.w += rv * wrow[3];
    }
    #pragma unroll
    for (int o = 1; o <= 4; o <<= 1) {
        pc.x += __shfl_xor_sync(0xffffffffu, pc.x, o);
        pc.y += __shfl_xor_sync(0xffffffffu, pc.y, o);
        pc.z += __shfl_xor_sync(0xffffffffu, pc.z, o);
        pc.w += __shfl_xor_sync(0xffffffffu, pc.w, o);
    }
    if (p == 0) {
        *(float4*)&g_h2[(size_t)d * HC2 + c0] = pc;
        float es = pc.x * sA2s[c0] + pc.y * sA2s[c0+1] + pc.z * sA2s[c0+2] + pc.w * sA2s[c0+3];
        float ed = pc.x * sA2d[c0] + pc.y * sA2d[c0+1] + pc.z * sA2d[c0+2] + pc.w * sA2d[c0+3];
        g_es2[(size_t)d * HEADS + e] = es;
        g_ed2[(size_t)d * HEADS + e] = ed;
    }
}

// ---------------- agg2: full-lane aggregation (no shfls in loop) + pool ------
// lane (le, lh): edge slot le, head lh == float4 part lh (C2 == 4).
__global__ __launch_bounds__(256) void agg2_kernel(const float* __restrict__ b2,
                                                   const void* __restrict__ batch) {
    __shared__ __align__(16) float sB2[HC2];
    if (threadIdx.x < HC2) sB2[threadIdx.x] = b2[threadIdx.x];
    __syncthreads();

    const int warp = (blockIdx.x * blockDim.x + threadIdx.x) >> 5;
    if (warp >= N_NODES) return;
    const int lane = threadIdx.x & 31;
    const int d    = warp;
    const int beg  = g_off[d];
    const int end  = g_off[d + 1];
    const int le = lane >> 2, lh = lane & 3;

    const float edv_s = g_ed2[(size_t)d * 4 + lh];

    float  den_l = 0.f;
    float4 acc = make_float4(0,0,0,0);

    for (int base = beg; base < end; base += 8) {
        const int idx = base + le;
        if (idx < end) {
            int s = g_csr[idx];
            float es_s = g_es2[(size_t)s * 4 + lh];
            float w = __expf(lrelu(es_s + edv_s));
            den_l += w;
            float4 hv = *(const float4*)(g_h2 + (size_t)s * HC2 + lh * 4);
            acc.x += w * hv.x; acc.y += w * hv.y;
            acc.z += w * hv.z; acc.w += w * hv.w;
        }
    }

    // reduce over edge slots (xor 4, 8, 16); lanes 0..3 then hold part 0..3
    #pragma unroll
    for (int o = 4; o <= 16; o <<= 1) {
        den_l += __shfl_xor_sync(0xffffffffu, den_l, o);
        acc.x += __shfl_xor_sync(0xffffffffu, acc.x, o);
        acc.y += __shfl_xor_sync(0xffffffffu, acc.y, o);
        acc.z += __shfl_xor_sync(0xffffffffu, acc.z, o);
        acc.w += __shfl_xor_sync(0xffffffffu, acc.w, o);
    }

    if (lane < 4) {
        int g;
        if (g_is64) g = (int)((const long long*)batch)[d];
        else        g = ((const int*)batch)[d];
        const float ih = 1.f / (den_l + 1e-16f);
        float4 bb = *(const float4*)&sB2[lane * 4];
        float o0 = fmaxf(acc.x * ih + bb.x, 0.f);
        float o1 = fmaxf(acc.y * ih + bb.y, 0.f);
        float o2 = fmaxf(acc.z * ih + bb.z, 0.f);
        float o3 = fmaxf(acc.w * ih + bb.w, 0.f);
        red4(g_pool + g * HC2 + lane * 4, o0, o1, o2, o3);
        if (lane == 0) atomicAdd(&g_cnt[g], 1.f);
    }
}

// ---------------- final ----------------
__global__ void final_kernel(const float* __restrict__ Wf, const float* __restrict__ bf,
                             float* __restrict__ out) {
    const int t = threadIdx.x;
    if (t >= N_GRAPHS * OUT_DIM) return;
    const int g = t / OUT_DIM;
    const int o = t % OUT_DIM;
    const float c = fmaxf(g_cnt[g], 1.f);
    float acc = bf[o];
    #pragma unroll
    for (int j = 0; j < HC2; j++)
        acc += (g_pool[g * HC2 + j] / c) * Wf[j * OUT_DIM + o];
    out[t] = acc;
}

// ---------------- stream/event holder ----------------
struct StreamHolder {
    cudaStream_t s2 = nullptr;
    cudaEvent_t  ev0 = nullptr, ev1 = nullptr;
    bool ok = false;
    StreamHolder() {
        if (cudaStreamCreateWithFlags(&s2, cudaStreamNonBlocking) != cudaSuccess) return;
        if (cudaEventCreateWithFlags(&ev0, cudaEventDisableTiming) != cudaSuccess) return;
        if (cudaEventCreateWithFlags(&ev1, cudaEventDisableTiming) != cudaSuccess) return;
        ok = true;
    }
};
static StreamHolder g_sh;

// ---------------- launch ----------------
extern "C" void kernel_launch(void* const* d_in, const int* in_sizes, int n_in,
                              void* d_out, int out_size) {
    const float* x       = (const float*)d_in[0];
    const void*  eidx    = d_in[1];
    const void*  batch   = d_in[2];
    const float* W1      = (const float*)d_in[3];
    const float* asrc1   = (const float*)d_in[4];
    const float* adst1   = (const float*)d_in[5];
    const float* b1      = (const float*)d_in[6];
    const float* W2      = (const float*)d_in[7];
    const float* asrc2   = (const float*)d_in[8];
    const float* adst2   = (const float*)d_in[9];
    const float* b2      = (const float*)d_in[10];
    const float* Wf      = (const float*)d_in[11];
    const float* bf      = (const float*)d_in[12];
    float* out = (float*)d_out;

    const int TB = 256;
    const int edgeGrid = (E_TOT + TB - 1) / TB;
    const int nodeGrid = (N_NODES + TB - 1) / TB;
    const int aggGrid  = (N_NODES * 32 + TB - 1) / TB;

    if (g_sh.ok) {
        // main stream goes straight to gemm1 (no dependency on detect/init/CSR);
        // s2 runs detect + init + CSR build concurrently.
        cudaEventRecord(g_sh.ev0, 0);
        cudaStreamWaitEvent(g_sh.s2, g_sh.ev0, 0);

        detect_kernel<<<1, 256, 0, g_sh.s2>>>(eidx);
        init_kernel<<<nodeGrid, TB, 0, g_sh.s2>>>();
        count_kernel<<<edgeGrid, TB, 0, g_sh.s2>>>(eidx);
        scan1_kernel<<<N_SCAN_BLOCKS, SCAN_BS, 0, g_sh.s2>>>();
        scan2_kernel<<<1, 128, 0, g_sh.s2>>>();
        scan3_kernel<<<N_SCAN_BLOCKS, SCAN_BS, 0, g_sh.s2>>>();
        scatter_kernel<<<edgeGrid, TB, 0, g_sh.s2>>>(eidx);
        cudaEventRecord(g_sh.ev1, g_sh.s2);

        gemm1_kernel<<<(N_NODES + G1_BN - 1) / G1_BN, 128>>>(x, W1, asrc1, adst1);

        cudaStreamWaitEvent(0, g_sh.ev1, 0);
    } else {
        detect_kernel<<<1, 256>>>(eidx);
        init_kernel<<<nodeGrid, TB>>>();
        count_kernel<<<edgeGrid, TB>>>(eidx);
        scan1_kernel<<<N_SCAN_BLOCKS, SCAN_BS>>>();
        scan2_kernel<<<1, 128>>>();
        scan3_kernel<<<N_SCAN_BLOCKS, SCAN_BS>>>();
        scatter_kernel<<<edgeGrid, TB>>>(eidx);
        gemm1_kernel<<<(N_NODES + G1_BN - 1) / G1_BN, 128>>>(x, W1, asrc1, adst1);
    }

    agg1_kernel<<<aggGrid, TB>>>(b1, W2, asrc2, adst2);
    agg2_kernel<<<aggGrid, TB>>>(b2, batch);
    final_kernel<<<1, N_GRAPHS * OUT_DIM>>>(Wf, bf, out);
}